// round 2
// baseline (speedup 1.0000x reference)
#include <cuda_runtime.h>
#include <math.h>

#define T_STEPS 128
#define BATCH   128
#define SAMP    8
#define DIN     64
#define RDIM    256
#define ZDIM    128
#define HDIM    512
#define BS      1024   /* BATCH*SAMP */
#define TB      16384  /* T_STEPS*BATCH */

#define DT       0.05f
#define SQRT_DT  0.22360679774997896f
#define LOG_2PI  1.8378770664093453f

// ---------------- scratch (static device globals; no runtime alloc) -------
__device__ __align__(16) float g_Hh[TB * HDIM];     // h @ Wd1[:R] + bd1       [T,B,H]
__device__ __align__(16) float g_Hhpos[TB * HDIM];  // (h+hpos)@Wd1[:R] + bd1  [T,B,H]
__device__ __align__(16) float g_Hph[TB * HDIM];    // h @ Wp1[:R] + bp1       [T,B,H]
__device__ __align__(16) float g_Hf[TB * HDIM];     // relu(h@Wf1+bf1)         [T,B,H]
__device__ __align__(16) float g_diff[TB * ZDIM];   // exp(Hf@Wf2+bf2)         [T,B,Z]
__device__ __align__(16) float g_Mt[T_STEPS * BATCH];
__device__ __align__(16) float g_z[BS * ZDIM];      // state z [B*S, Z]
__device__ __align__(16) float g_Hz[BS * HDIM];     // z @ Wd1[R:,:]
__device__ __align__(16) float g_Hpz[BS * HDIM];    // z @ Wp1[R:,:]
__device__ __align__(16) float g_P[BS * ZDIM];      // p preact [B*S, 2*Din]
__device__ float g_kldpart[T_STEPS * 64];
__device__ float g_reconpart[T_STEPS * 64];

// ---------------- z0: cov -> CH -> Z (relu, tanh) --------------------------
__global__ void z0_kernel(const float* __restrict__ cov,
                          const float* __restrict__ Wc1, const float* __restrict__ bc1,
                          const float* __restrict__ Wc2, const float* __restrict__ bc2)
{
    int b = blockIdx.x;     // 128 blocks
    int tid = threadIdx.x;  // 128 threads
    __shared__ float sc[32];
    __shared__ float sh[64];
    if (tid < 32) sc[tid] = cov[b * 32 + tid];
    __syncthreads();
    if (tid < 64) {
        float acc = bc1[tid];
        #pragma unroll
        for (int c = 0; c < 32; c++) acc = fmaf(sc[c], Wc1[c * 64 + tid], acc);
        sh[tid] = fmaxf(acc, 0.f);
    }
    __syncthreads();
    float acc = bc2[tid];
    #pragma unroll
    for (int k = 0; k < 64; k++) acc = fmaf(sh[k], Wc2[k * 128 + tid], acc);
    float z = tanhf(acc);
    #pragma unroll
    for (int s = 0; s < SAMP; s++)
        g_z[(b * SAMP + s) * ZDIM + tid] = z;
}

// ---------------- Mt = mean(M, axis=-1) ------------------------------------
__global__ void mt_kernel(const float* __restrict__ M)
{
    int i = blockIdx.x * blockDim.x + threadIdx.x;   // 16384 rows
    const float4* p = (const float4*)(M + (size_t)i * DIN);
    float s = 0.f;
    #pragma unroll
    for (int j = 0; j < DIN / 4; j++) { float4 v = p[j]; s += v.x + v.y + v.z + v.w; }
    g_Mt[i] = s * (1.f / (float)DIN);
}

// ---------------- generic fp32 tiled GEMM: C = act(A@W + bias) -------------
// A:[M,K] ld=K, W:[K,N] ld=N, C:[M,N] ld=N.  ACT: 0 none, 1 relu, 2 exp.
// SUMA: A := A + A2 elementwise. M,N mult of 64, K mult of 32.
template<int ACT, bool SUMA>
__global__ void gemm_f32(const float* __restrict__ A, const float* __restrict__ A2,
                         const float* __restrict__ W, const float* __restrict__ bias,
                         float* __restrict__ C, int M, int N, int K)
{
    __shared__ float sA[64][33];
    __shared__ float sB[32][68];
    const int bm = blockIdx.y * 64;
    const int bn = blockIdx.x * 64;
    const int tid = threadIdx.x;       // 256
    const int tx = tid & 15;
    const int ty = tid >> 4;
    float acc[4][4] = {};
    for (int k0 = 0; k0 < K; k0 += 32) {
        #pragma unroll
        for (int l = 0; l < 2; l++) {
            int v  = tid + l * 256;       // 0..511
            int r  = v >> 3;
            int c4 = (v & 7) * 4;
            float4 av = *(const float4*)&A[(size_t)(bm + r) * K + k0 + c4];
            if (SUMA) {
                float4 b4 = *(const float4*)&A2[(size_t)(bm + r) * K + k0 + c4];
                av.x += b4.x; av.y += b4.y; av.z += b4.z; av.w += b4.w;
            }
            sA[r][c4 + 0] = av.x; sA[r][c4 + 1] = av.y;
            sA[r][c4 + 2] = av.z; sA[r][c4 + 3] = av.w;
        }
        #pragma unroll
        for (int l = 0; l < 2; l++) {
            int v  = tid + l * 256;
            int r  = v >> 4;              // 0..31
            int c4 = (v & 15) * 4;
            *(float4*)&sB[r][c4] = *(const float4*)&W[(size_t)(k0 + r) * N + bn + c4];
        }
        __syncthreads();
        #pragma unroll
        for (int k = 0; k < 32; k++) {
            float a[4];
            #pragma unroll
            for (int i = 0; i < 4; i++) a[i] = sA[ty * 4 + i][k];
            float4 bv = *(const float4*)&sB[k][tx * 4];
            float b[4] = { bv.x, bv.y, bv.z, bv.w };
            #pragma unroll
            for (int i = 0; i < 4; i++)
                #pragma unroll
                for (int j = 0; j < 4; j++)
                    acc[i][j] = fmaf(a[i], b[j], acc[i][j]);
        }
        __syncthreads();
    }
    #pragma unroll
    for (int i = 0; i < 4; i++) {
        int r = bm + ty * 4 + i;
        #pragma unroll
        for (int j = 0; j < 4; j++) {
            int c = bn + tx * 4 + j;
            float v = acc[i][j] + (bias ? bias[c] : 0.f);
            if (ACT == 1) v = fmaxf(v, 0.f);
            if (ACT == 2) v = expf(v);
            C[(size_t)r * N + c] = v;
        }
    }
}

// ---------------- dual GEMM: Hpz = z@Wp1z, Hz = z@Wd1z (same A) ------------
// A = g_z [1024,128]. W half selected by blockIdx.x. 64x64 tiles, K=128.
__global__ void gemm_dual(const float* __restrict__ Wp,   // Wp1 + R*H
                          const float* __restrict__ Wd)   // Wd1 + R*H
{
    __shared__ float sA[64][33];
    __shared__ float sB[32][68];
    const int half = blockIdx.x >> 3;              // 0: Hpz/Wp, 1: Hz/Wd
    const float* __restrict__ W = half ? Wd : Wp;
    float* __restrict__ C       = half ? g_Hz : g_Hpz;
    const int bm = blockIdx.y * 64;
    const int bn = (blockIdx.x & 7) * 64;
    const int tid = threadIdx.x;       // 256
    const int tx = tid & 15;
    const int ty = tid >> 4;
    float acc[4][4] = {};
    for (int k0 = 0; k0 < ZDIM; k0 += 32) {
        #pragma unroll
        for (int l = 0; l < 2; l++) {
            int v  = tid + l * 256;
            int r  = v >> 3;
            int c4 = (v & 7) * 4;
            float4 av = *(const float4*)&g_z[(size_t)(bm + r) * ZDIM + k0 + c4];
            sA[r][c4 + 0] = av.x; sA[r][c4 + 1] = av.y;
            sA[r][c4 + 2] = av.z; sA[r][c4 + 3] = av.w;
        }
        #pragma unroll
        for (int l = 0; l < 2; l++) {
            int v  = tid + l * 256;
            int r  = v >> 4;
            int c4 = (v & 15) * 4;
            *(float4*)&sB[r][c4] = *(const float4*)&W[(size_t)(k0 + r) * HDIM + bn + c4];
        }
        __syncthreads();
        #pragma unroll
        for (int k = 0; k < 32; k++) {
            float a[4];
            #pragma unroll
            for (int i = 0; i < 4; i++) a[i] = sA[ty * 4 + i][k];
            float4 bv = *(const float4*)&sB[k][tx * 4];
            #pragma unroll
            for (int i = 0; i < 4; i++) {
                acc[i][0] = fmaf(a[i], bv.x, acc[i][0]);
                acc[i][1] = fmaf(a[i], bv.y, acc[i][1]);
                acc[i][2] = fmaf(a[i], bv.z, acc[i][2]);
                acc[i][3] = fmaf(a[i], bv.w, acc[i][3]);
            }
        }
        __syncthreads();
    }
    #pragma unroll
    for (int i = 0; i < 4; i++) {
        int r = bm + ty * 4 + i;
        #pragma unroll
        for (int j = 0; j < 4; j++)
            C[(size_t)r * HDIM + bn + tx * 4 + j] = acc[i][j];
    }
}

// ---------------- fused drift head + z update + KLD partial ----------------
// prior = 0.1*tanh(relu(Hh[t]+Hz) @ Wd2 + bd2)
// poster= 0.1*tanh(relu(Hhpos[t]+Hz) @ Wd2 + bd2)   (shares the Wd2 B-tile)
// z += dt*poster + sqrt_dt*diff*eps;  kld partial += ((prior-poster)/diff)^2
// Tiles: BM=64 rows, BN=32 z-cols, 256 threads, thread tile 2x4 (x2 acc sets).
__global__ void drift_fused(int t, const float* __restrict__ Wd2,
                            const float* __restrict__ bd2,
                            const float* __restrict__ noise)
{
    __shared__ float sAp[64][33];
    __shared__ float sAq[64][33];
    __shared__ float sB[32][36];
    const int bm = blockIdx.y * 64;     // 16 blocks y
    const int bn = blockIdx.x * 32;     // 4 blocks x
    const int tid = threadIdx.x;        // 256
    const int tx = tid & 7;             // col quad
    const int ty = tid >> 3;            // row pair
    float accp[2][4] = {};
    float accq[2][4] = {};
    const size_t hoff = (size_t)t * BATCH * HDIM;

    for (int k0 = 0; k0 < HDIM; k0 += 32) {
        #pragma unroll
        for (int l = 0; l < 2; l++) {
            int v  = tid + l * 256;      // 512 float4 slots
            int r  = v >> 3;
            int c4 = (v & 7) * 4;
            int rr = bm + r;
            int b  = rr >> 3;
            size_t hidx = hoff + (size_t)b * HDIM + k0 + c4;
            size_t zidx = (size_t)rr * HDIM + k0 + c4;
            float4 z4 = *(const float4*)&g_Hz[zidx];
            float4 h4 = *(const float4*)&g_Hh[hidx];
            float4 q4 = *(const float4*)&g_Hhpos[hidx];
            sAp[r][c4 + 0] = fmaxf(h4.x + z4.x, 0.f);
            sAp[r][c4 + 1] = fmaxf(h4.y + z4.y, 0.f);
            sAp[r][c4 + 2] = fmaxf(h4.z + z4.z, 0.f);
            sAp[r][c4 + 3] = fmaxf(h4.w + z4.w, 0.f);
            sAq[r][c4 + 0] = fmaxf(q4.x + z4.x, 0.f);
            sAq[r][c4 + 1] = fmaxf(q4.y + z4.y, 0.f);
            sAq[r][c4 + 2] = fmaxf(q4.z + z4.z, 0.f);
            sAq[r][c4 + 3] = fmaxf(q4.w + z4.w, 0.f);
        }
        {
            int r  = tid >> 3;
            int c4 = (tid & 7) * 4;
            *(float4*)&sB[r][c4] = *(const float4*)&Wd2[(size_t)(k0 + r) * ZDIM + bn + c4];
        }
        __syncthreads();
        #pragma unroll
        for (int k = 0; k < 32; k++) {
            float ap0 = sAp[ty * 2 + 0][k];
            float ap1 = sAp[ty * 2 + 1][k];
            float aq0 = sAq[ty * 2 + 0][k];
            float aq1 = sAq[ty * 2 + 1][k];
            float4 bv = *(const float4*)&sB[k][tx * 4];
            accp[0][0] = fmaf(ap0, bv.x, accp[0][0]);
            accp[0][1] = fmaf(ap0, bv.y, accp[0][1]);
            accp[0][2] = fmaf(ap0, bv.z, accp[0][2]);
            accp[0][3] = fmaf(ap0, bv.w, accp[0][3]);
            accp[1][0] = fmaf(ap1, bv.x, accp[1][0]);
            accp[1][1] = fmaf(ap1, bv.y, accp[1][1]);
            accp[1][2] = fmaf(ap1, bv.z, accp[1][2]);
            accp[1][3] = fmaf(ap1, bv.w, accp[1][3]);
            accq[0][0] = fmaf(aq0, bv.x, accq[0][0]);
            accq[0][1] = fmaf(aq0, bv.y, accq[0][1]);
            accq[0][2] = fmaf(aq0, bv.z, accq[0][2]);
            accq[0][3] = fmaf(aq0, bv.w, accq[0][3]);
            accq[1][0] = fmaf(aq1, bv.x, accq[1][0]);
            accq[1][1] = fmaf(aq1, bv.y, accq[1][1]);
            accq[1][2] = fmaf(aq1, bv.z, accq[1][2]);
            accq[1][3] = fmaf(aq1, bv.w, accq[1][3]);
        }
        __syncthreads();
    }

    // epilogue: prior/poster -> z update + kld
    float local = 0.f;
    #pragma unroll
    for (int i = 0; i < 2; i++) {
        int r = bm + ty * 2 + i;
        int b = r >> 3;
        int s = r & 7;
        #pragma unroll
        for (int j = 0; j < 4; j++) {
            int c = bn + tx * 4 + j;
            float bias   = bd2[c];
            float prior  = 0.1f * tanhf(accp[i][j] + bias);
            float poster = 0.1f * tanhf(accq[i][j] + bias);
            float d   = g_diff[((size_t)(t * BATCH + b)) * ZDIM + c];
            float eps = noise[(((size_t)(t * BATCH + b)) * SAMP + s) * ZDIM + c];
            size_t zi = (size_t)r * ZDIM + c;
            g_z[zi] = g_z[zi] + DT * poster + SQRT_DT * d * eps;
            float err = (prior - poster) / d;
            local = fmaf(err, err, local);
        }
    }
    __shared__ float red[256];
    red[tid] = local;
    __syncthreads();
    for (int s2 = 128; s2 > 0; s2 >>= 1) {
        if (tid < s2) red[tid] += red[tid + s2];
        __syncthreads();
    }
    if (tid == 0)
        g_kldpart[t * 64 + blockIdx.y * 4 + blockIdx.x] = red[0];
}

// ---------------- p head: g_P = relu(Hph[t]+Hpz) @ Wp2 + bp2 ----------------
__global__ void p_head(int t, const float* __restrict__ W,
                       const float* __restrict__ bias)
{
    __shared__ float sA[64][33];
    __shared__ float sB[32][36];
    const int bm = blockIdx.y * 64;
    const int bn = blockIdx.x * 32;
    const int tid = threadIdx.x;   // 256
    const int tx = tid & 7;
    const int ty = tid >> 3;
    float acc[2][4] = {};
    const size_t hoff = (size_t)t * BATCH * HDIM;

    for (int k0 = 0; k0 < HDIM; k0 += 32) {
        #pragma unroll
        for (int l = 0; l < 2; l++) {
            int v  = tid + l * 256;
            int r  = v >> 3;
            int c4 = (v & 7) * 4;
            int rr = bm + r;
            int b  = rr >> 3;
            float4 h4 = *(const float4*)&g_Hph[hoff + (size_t)b * HDIM + k0 + c4];
            float4 z4 = *(const float4*)&g_Hpz[(size_t)rr * HDIM + k0 + c4];
            sA[r][c4 + 0] = fmaxf(h4.x + z4.x, 0.f);
            sA[r][c4 + 1] = fmaxf(h4.y + z4.y, 0.f);
            sA[r][c4 + 2] = fmaxf(h4.z + z4.z, 0.f);
            sA[r][c4 + 3] = fmaxf(h4.w + z4.w, 0.f);
        }
        {
            int r  = tid >> 3;
            int c4 = (tid & 7) * 4;
            *(float4*)&sB[r][c4] = *(const float4*)&W[(size_t)(k0 + r) * ZDIM + bn + c4];
        }
        __syncthreads();
        #pragma unroll
        for (int k = 0; k < 32; k++) {
            float a0 = sA[ty * 2 + 0][k];
            float a1 = sA[ty * 2 + 1][k];
            float4 bv = *(const float4*)&sB[k][tx * 4];
            acc[0][0] = fmaf(a0, bv.x, acc[0][0]);
            acc[0][1] = fmaf(a0, bv.y, acc[0][1]);
            acc[0][2] = fmaf(a0, bv.z, acc[0][2]);
            acc[0][3] = fmaf(a0, bv.w, acc[0][3]);
            acc[1][0] = fmaf(a1, bv.x, acc[1][0]);
            acc[1][1] = fmaf(a1, bv.y, acc[1][1]);
            acc[1][2] = fmaf(a1, bv.z, acc[1][2]);
            acc[1][3] = fmaf(a1, bv.w, acc[1][3]);
        }
        __syncthreads();
    }
    #pragma unroll
    for (int i = 0; i < 2; i++) {
        int r = bm + ty * 2 + i;
        #pragma unroll
        for (int j = 0; j < 4; j++) {
            int c = bn + tx * 4 + j;
            g_P[(size_t)r * ZDIM + c] = acc[i][j] + bias[c];
        }
    }
}

// ---------------- NLL / recon partial ---------------------------------------
__global__ void step_recon(int t, const float* __restrict__ X)
{
    const int blk = blockIdx.x;   // 64
    const int tid = threadIdx.x;  // 256
    float local = 0.f;
    #pragma unroll
    for (int l = 0; l < 4; l++) {
        int e    = blk * 1024 + l * 256 + tid;  // 0..65535
        int row  = e >> 6;                      // 0..1023
        int dcol = e & 63;
        int b    = row >> 3;
        float mean   = g_P[row * ZDIM + dcol];
        float logvar = g_P[row * ZDIM + dcol + 64];
        float x  = X[((size_t)(t * BATCH + b)) * DIN + dcol];
        float dv = x - mean;
        float nll = 0.5f * (LOG_2PI + logvar + dv * dv * expf(-logvar));
        local = fmaf(g_Mt[t * BATCH + b], nll, local);
    }
    __shared__ float red[256];
    red[tid] = local;
    __syncthreads();
    for (int s2 = 128; s2 > 0; s2 >>= 1) {
        if (tid < s2) red[tid] += red[tid + s2];
        __syncthreads();
    }
    if (tid == 0) g_reconpart[t * 64 + blk] = red[0];
}

// ---------------- final fixed-order reduction + output ---------------------
__global__ void copy_z(float* __restrict__ out)
{
    int i = blockIdx.x * blockDim.x + threadIdx.x;
    out[i] = g_z[i];
}

__global__ void finalize(float* __restrict__ out, int out_size)
{
    int tid = threadIdx.x;   // 256
    float k = 0.f, r = 0.f;
    for (int i = tid; i < T_STEPS * 64; i += 256) k += g_kldpart[i];
    for (int i = tid; i < T_STEPS * 64; i += 256) r += g_reconpart[i];
    __shared__ float rk[256], rr[256];
    rk[tid] = k; rr[tid] = r;
    __syncthreads();
    for (int s = 128; s > 0; s >>= 1) {
        if (tid < s) { rk[tid] += rk[tid + s]; rr[tid] += rr[tid + s]; }
        __syncthreads();
    }
    if (tid == 0) {
        float kld   = rk[0] * (0.5f * DT / (float)BS);
        float recon = rr[0] * (1.f / (float)BS);
        out[out_size - 3] = recon + kld;  // loss_total (LAMBDA=1)
        out[out_size - 2] = recon;        // loss_recon
        out[out_size - 1] = kld;          // loss_kld
    }
}

// ---------------- launch ----------------------------------------------------
extern "C" void kernel_launch(void* const* d_in, const int* in_sizes, int n_in,
                              void* d_out, int out_size)
{
    const float* X     = (const float*)d_in[0];
    const float* M     = (const float*)d_in[1];
    const float* cov   = (const float*)d_in[2];
    const float* ph    = (const float*)d_in[3];
    const float* phpos = (const float*)d_in[4];
    const float* noise = (const float*)d_in[5];
    const float* Wc1 = (const float*)d_in[6],  *bc1 = (const float*)d_in[7];
    const float* Wc2 = (const float*)d_in[8],  *bc2 = (const float*)d_in[9];
    const float* Wd1 = (const float*)d_in[10], *bd1 = (const float*)d_in[11];
    const float* Wd2 = (const float*)d_in[12], *bd2 = (const float*)d_in[13];
    const float* Wf1 = (const float*)d_in[14], *bf1 = (const float*)d_in[15];
    const float* Wf2 = (const float*)d_in[16], *bf2 = (const float*)d_in[17];
    const float* Wp1 = (const float*)d_in[18], *bp1 = (const float*)d_in[19];
    const float* Wp2 = (const float*)d_in[20], *bp2 = (const float*)d_in[21];
    float* out = (float*)d_out;

    float *pHh, *pHhpos, *pHph, *pHf, *pdiff, *pz, *pHz;
    cudaGetSymbolAddress((void**)&pHh,    g_Hh);
    cudaGetSymbolAddress((void**)&pHhpos, g_Hhpos);
    cudaGetSymbolAddress((void**)&pHph,   g_Hph);
    cudaGetSymbolAddress((void**)&pHf,    g_Hf);
    cudaGetSymbolAddress((void**)&pdiff,  g_diff);
    cudaGetSymbolAddress((void**)&pz,     g_z);
    cudaGetSymbolAddress((void**)&pHz,    g_Hz);

    // ---- precompute (parallel over all T) ----
    z0_kernel<<<BATCH, 128>>>(cov, Wc1, bc1, Wc2, bc2);
    mt_kernel<<<64, 256>>>(M);
    gemm_f32<0, false><<<dim3(HDIM/64, TB/64), 256>>>(ph,  nullptr, Wd1, bd1, pHh,    TB, HDIM, RDIM);
    gemm_f32<0, true ><<<dim3(HDIM/64, TB/64), 256>>>(ph,  phpos,   Wd1, bd1, pHhpos, TB, HDIM, RDIM);
    gemm_f32<0, false><<<dim3(HDIM/64, TB/64), 256>>>(ph,  nullptr, Wp1, bp1, pHph,   TB, HDIM, RDIM);
    gemm_f32<1, false><<<dim3(HDIM/64, TB/64), 256>>>(ph,  nullptr, Wf1, bf1, pHf,    TB, HDIM, RDIM);
    gemm_f32<2, false><<<dim3(ZDIM/64, TB/64), 256>>>(pHf, nullptr, Wf2, bf2, pdiff,  TB, ZDIM, HDIM);

    // initial Hz = z0 @ Wd1[R:,:]
    gemm_f32<0, false><<<dim3(HDIM/64, BS/64), 256>>>(pz, nullptr, Wd1 + RDIM * HDIM,
                                                      nullptr, pHz, BS, HDIM, ZDIM);

    // ---- sequential scan: 4 kernels/step ----
    const float* Wp1z = Wp1 + RDIM * HDIM;
    const float* Wd1z = Wd1 + RDIM * HDIM;
    for (int t = 0; t < T_STEPS; t++) {
        drift_fused<<<dim3(4, 16), 256>>>(t, Wd2, bd2, noise);  // z updated, kld partial
        gemm_dual<<<dim3(16, 16), 256>>>(Wp1z, Wd1z);           // Hpz(t) + Hz(t+1)
        p_head<<<dim3(4, 16), 256>>>(t, Wp2, bp2);
        step_recon<<<64, 256>>>(t, X);
    }

    // ---- outputs ----
    copy_z<<<(BS * ZDIM) / 256, 256>>>(out);
    finalize<<<1, 256>>>(out, out_size);
}

// round 3
// speedup vs baseline: 1.2013x; 1.2013x over previous
#include <cuda_runtime.h>
#include <math.h>

#define T_STEPS 128
#define BATCH   128
#define SAMP    8
#define DIN     64
#define RDIM    256
#define ZDIM    128
#define HDIM    512
#define BS      1024   /* BATCH*SAMP */
#define TB      16384  /* T_STEPS*BATCH */
#define NBLK    128
#define NTHR    256

#define DT       0.05f
#define SQRT_DT  0.22360679774997896f
#define LOG_2PI  1.8378770664093453f

// ---------------- scratch (static device globals; no runtime alloc) -------
__device__ __align__(16) float g_Hh[TB * HDIM];
__device__ __align__(16) float g_Hhpos[TB * HDIM];
__device__ __align__(16) float g_Hph[TB * HDIM];
__device__ __align__(16) float g_Hf[TB * HDIM];
__device__ __align__(16) float g_diff[TB * ZDIM];
__device__ __align__(16) float g_Mt[T_STEPS * BATCH];
__device__ __align__(16) float g_z[BS * ZDIM];
__device__ __align__(16) float g_Hz[BS * HDIM];
__device__ __align__(16) float g_Hpz[BS * HDIM];
__device__ float g_kldpart[T_STEPS * NBLK];
__device__ float g_reconpart[T_STEPS * NBLK];

// grid barrier state (returns to all-zero after an even number of barriers)
__device__ unsigned g_barcnt;
__device__ volatile unsigned g_barsense;

__device__ __forceinline__ float4 ldcg4(const float* p) {
    return __ldcg((const float4*)p);
}

// ---------------- z0: cov -> CH -> Z (relu, tanh) --------------------------
__global__ void z0_kernel(const float* __restrict__ cov,
                          const float* __restrict__ Wc1, const float* __restrict__ bc1,
                          const float* __restrict__ Wc2, const float* __restrict__ bc2)
{
    int b = blockIdx.x;
    int tid = threadIdx.x;  // 128
    __shared__ float sc[32];
    __shared__ float sh[64];
    if (tid < 32) sc[tid] = cov[b * 32 + tid];
    __syncthreads();
    if (tid < 64) {
        float acc = bc1[tid];
        #pragma unroll
        for (int c = 0; c < 32; c++) acc = fmaf(sc[c], Wc1[c * 64 + tid], acc);
        sh[tid] = fmaxf(acc, 0.f);
    }
    __syncthreads();
    float acc = bc2[tid];
    #pragma unroll
    for (int k = 0; k < 64; k++) acc = fmaf(sh[k], Wc2[k * 128 + tid], acc);
    float z = tanhf(acc);
    #pragma unroll
    for (int s = 0; s < SAMP; s++)
        g_z[(b * SAMP + s) * ZDIM + tid] = z;
}

// ---------------- Mt = mean(M, axis=-1) ------------------------------------
__global__ void mt_kernel(const float* __restrict__ M)
{
    int i = blockIdx.x * blockDim.x + threadIdx.x;
    const float4* p = (const float4*)(M + (size_t)i * DIN);
    float s = 0.f;
    #pragma unroll
    for (int j = 0; j < DIN / 4; j++) { float4 v = p[j]; s += v.x + v.y + v.z + v.w; }
    g_Mt[i] = s * (1.f / (float)DIN);
}

// ---------------- generic fp32 tiled GEMM (precompute) ---------------------
template<int ACT, bool SUMA>
__global__ void gemm_f32(const float* __restrict__ A, const float* __restrict__ A2,
                         const float* __restrict__ W, const float* __restrict__ bias,
                         float* __restrict__ C, int M, int N, int K)
{
    __shared__ float sA[64][33];
    __shared__ float sB[32][68];
    const int bm = blockIdx.y * 64;
    const int bn = blockIdx.x * 64;
    const int tid = threadIdx.x;
    const int tx = tid & 15;
    const int ty = tid >> 4;
    float acc[4][4] = {};
    for (int k0 = 0; k0 < K; k0 += 32) {
        #pragma unroll
        for (int l = 0; l < 2; l++) {
            int v  = tid + l * 256;
            int r  = v >> 3;
            int c4 = (v & 7) * 4;
            float4 av = *(const float4*)&A[(size_t)(bm + r) * K + k0 + c4];
            if (SUMA) {
                float4 b4 = *(const float4*)&A2[(size_t)(bm + r) * K + k0 + c4];
                av.x += b4.x; av.y += b4.y; av.z += b4.z; av.w += b4.w;
            }
            sA[r][c4 + 0] = av.x; sA[r][c4 + 1] = av.y;
            sA[r][c4 + 2] = av.z; sA[r][c4 + 3] = av.w;
        }
        #pragma unroll
        for (int l = 0; l < 2; l++) {
            int v  = tid + l * 256;
            int r  = v >> 4;
            int c4 = (v & 15) * 4;
            *(float4*)&sB[r][c4] = *(const float4*)&W[(size_t)(k0 + r) * N + bn + c4];
        }
        __syncthreads();
        #pragma unroll
        for (int k = 0; k < 32; k++) {
            float a[4];
            #pragma unroll
            for (int i = 0; i < 4; i++) a[i] = sA[ty * 4 + i][k];
            float4 bv = *(const float4*)&sB[k][tx * 4];
            #pragma unroll
            for (int i = 0; i < 4; i++) {
                acc[i][0] = fmaf(a[i], bv.x, acc[i][0]);
                acc[i][1] = fmaf(a[i], bv.y, acc[i][1]);
                acc[i][2] = fmaf(a[i], bv.z, acc[i][2]);
                acc[i][3] = fmaf(a[i], bv.w, acc[i][3]);
            }
        }
        __syncthreads();
    }
    #pragma unroll
    for (int i = 0; i < 4; i++) {
        int r = bm + ty * 4 + i;
        #pragma unroll
        for (int j = 0; j < 4; j++) {
            int c = bn + tx * 4 + j;
            float v = acc[i][j] + (bias ? bias[c] : 0.f);
            if (ACT == 1) v = fmaxf(v, 0.f);
            if (ACT == 2) v = expf(v);
            C[(size_t)r * N + c] = v;
        }
    }
}

// ================= persistent scan kernel ==================================

__device__ __forceinline__ void gridbar(unsigned& ls)
{
    ls ^= 1u;
    __syncthreads();
    if (threadIdx.x == 0) {
        __threadfence();
        if (atomicAdd(&g_barcnt, 1u) == NBLK - 1) {
            g_barcnt = 0;
            __threadfence();
            g_barsense = ls;
        } else {
            while (g_barsense != ls) __nanosleep(32);
            __threadfence();
        }
    }
    __syncthreads();
}

// Phase A: drift GEMM (dual prior/poster) + z update (reg-resident) + KLD.
// Block b: rows (b>>1)*16..+16, cols (b&1)*64..+64.
__device__ void phaseA(int t, const float* __restrict__ Wd2,
                       const float* __restrict__ bd2,
                       const float* __restrict__ noise,
                       float* sh, float zreg[4])
{
    const int b = blockIdx.x;
    const int r0 = (b >> 1) * 16;
    const int c0 = (b & 1) * 64;
    const int tid = threadIdx.x;
    const int ty = tid >> 4;   // row 0..15
    const int tx = tid & 15;   // col quad
    float* sAp = sh;           // [16][33]
    float* sAq = sh + 528;     // [16][33]
    float* sB  = sh + 1056;    // [32][68]
    float accp[4] = {0.f, 0.f, 0.f, 0.f};
    float accq[4] = {0.f, 0.f, 0.f, 0.f};
    const size_t hbase = (size_t)t * BATCH * HDIM;

    for (int k0 = 0; k0 < HDIM; k0 += 32) {
        {   // A tiles: 2 arrays x 128 float4 -> 256 threads, 1 each
            int arr  = tid >> 7;
            int slot = tid & 127;
            int r  = slot >> 3;
            int c4 = (slot & 7) * 4;
            int rr = r0 + r;
            int bi = rr >> 3;
            float4 z4 = ldcg4(&g_Hz[(size_t)rr * HDIM + k0 + c4]);
            const float* hsrc = arr ? g_Hhpos : g_Hh;
            const float4 h4 = *(const float4*)&hsrc[hbase + (size_t)bi * HDIM + k0 + c4];
            float* dst = (arr ? sAq : sAp) + r * 33 + c4;
            dst[0] = fmaxf(h4.x + z4.x, 0.f);
            dst[1] = fmaxf(h4.y + z4.y, 0.f);
            dst[2] = fmaxf(h4.z + z4.z, 0.f);
            dst[3] = fmaxf(h4.w + z4.w, 0.f);
        }
        #pragma unroll
        for (int l = 0; l < 2; l++) {   // B tile: 32x64 -> 512 float4
            int v  = tid + l * 256;
            int r  = v >> 4;
            int c4 = (v & 15) * 4;
            *(float4*)&sB[r * 68 + c4] =
                *(const float4*)&Wd2[(size_t)(k0 + r) * ZDIM + c0 + c4];
        }
        __syncthreads();
        #pragma unroll
        for (int k = 0; k < 32; k++) {
            float ap = sAp[ty * 33 + k];
            float aq = sAq[ty * 33 + k];
            float4 bv = *(float4*)&sB[k * 68 + tx * 4];
            accp[0] = fmaf(ap, bv.x, accp[0]);
            accp[1] = fmaf(ap, bv.y, accp[1]);
            accp[2] = fmaf(ap, bv.z, accp[2]);
            accp[3] = fmaf(ap, bv.w, accp[3]);
            accq[0] = fmaf(aq, bv.x, accq[0]);
            accq[1] = fmaf(aq, bv.y, accq[1]);
            accq[2] = fmaf(aq, bv.z, accq[2]);
            accq[3] = fmaf(aq, bv.w, accq[3]);
        }
        __syncthreads();
    }

    // epilogue: Euler-Maruyama z update (reg-resident) + KLD partial
    const int rr = r0 + ty;
    const int bi = rr >> 3;
    const int si = rr & 7;
    const float* drow = &g_diff[((size_t)t * BATCH + bi) * ZDIM];
    const float* nrow = &noise[(((size_t)t * BATCH + bi) * SAMP + si) * ZDIM];
    float kl = 0.f;
    #pragma unroll
    for (int j = 0; j < 4; j++) {
        int c = c0 + tx * 4 + j;
        float bias   = bd2[c];
        float prior  = 0.1f * tanhf(accp[j] + bias);
        float poster = 0.1f * tanhf(accq[j] + bias);
        float d   = drow[c];
        float eps = nrow[c];
        zreg[j] += DT * poster + SQRT_DT * d * eps;
        float err = (prior - poster) / d;
        kl = fmaf(err, err, kl);
    }
    __stcg((float4*)&g_z[(size_t)rr * ZDIM + c0 + tx * 4],
           make_float4(zreg[0], zreg[1], zreg[2], zreg[3]));

    sh[tid] = kl;
    __syncthreads();
    for (int s2 = 128; s2 > 0; s2 >>= 1) {
        if (tid < s2) sh[tid] += sh[tid + s2];
        __syncthreads();
    }
    if (tid == 0) g_kldpart[t * NBLK + b] = sh[0];
    __syncthreads();
}

// Phase B: Hpz = z@Wp1z and Hz = z@Wd1z. Block b: mat=b>>6, tile 64x128, K=128.
__device__ void phaseB(const float* __restrict__ Wp1z,
                       const float* __restrict__ Wd1z, float* sh)
{
    const int b = blockIdx.x;
    const int mat = b >> 6;
    const float* __restrict__ W = mat ? Wd1z : Wp1z;
    float* __restrict__ C = mat ? g_Hz : g_Hpz;
    const int idx = b & 63;
    const int r0 = (idx >> 2) * 64;
    const int c0 = (idx & 3) * 128;
    const int tid = threadIdx.x;
    const int ty = tid >> 5;   // 0..7 (8 rows each)
    const int tx = tid & 31;   // col quad
    float* sA = sh;            // [64][33]
    float* sB = sh + 2112;     // [32][132]
    float acc[8][4] = {};

    for (int k0 = 0; k0 < ZDIM; k0 += 32) {
        #pragma unroll
        for (int l = 0; l < 2; l++) {   // z tile: 64x32 -> 512 float4
            int v  = tid + l * 256;
            int r  = v >> 3;
            int c4 = (v & 7) * 4;
            float4 z4 = ldcg4(&g_z[(size_t)(r0 + r) * ZDIM + k0 + c4]);
            float* dst = &sA[r * 33 + c4];
            dst[0] = z4.x; dst[1] = z4.y; dst[2] = z4.z; dst[3] = z4.w;
        }
        #pragma unroll
        for (int l = 0; l < 4; l++) {   // W tile: 32x128 -> 1024 float4
            int v  = tid + l * 256;
            int r  = v >> 5;
            int c4 = (v & 31) * 4;
            *(float4*)&sB[r * 132 + c4] =
                *(const float4*)&W[(size_t)(k0 + r) * HDIM + c0 + c4];
        }
        __syncthreads();
        #pragma unroll
        for (int k = 0; k < 32; k++) {
            float4 bv = *(float4*)&sB[k * 132 + tx * 4];
            #pragma unroll
            for (int i = 0; i < 8; i++) {
                float a = sA[(ty * 8 + i) * 33 + k];
                acc[i][0] = fmaf(a, bv.x, acc[i][0]);
                acc[i][1] = fmaf(a, bv.y, acc[i][1]);
                acc[i][2] = fmaf(a, bv.z, acc[i][2]);
                acc[i][3] = fmaf(a, bv.w, acc[i][3]);
            }
        }
        __syncthreads();
    }
    #pragma unroll
    for (int i = 0; i < 8; i++)
        __stcg((float4*)&C[(size_t)(r0 + ty * 8 + i) * HDIM + c0 + tx * 4],
               make_float4(acc[i][0], acc[i][1], acc[i][2], acc[i][3]));
}

// Phase C: p head (mean/logvar dual acc, no P buffer) + recon partial.
// Block b: rows b*8..+8, mean cols 0..63 and logvar cols 64..127.
__device__ void phaseC(int t, const float* __restrict__ Wp2,
                       const float* __restrict__ bp2,
                       const float* __restrict__ X, float* sh)
{
    const int b = blockIdx.x;
    const int r0 = b * 8;
    const int tid = threadIdx.x;
    const int ty = tid >> 5;   // row 0..7
    const int tx = tid & 31;   // col pair
    float* sA = sh;            // [8][33]
    float* sB = sh + 264;      // [32][132]
    float am[2] = {0.f, 0.f};
    float al[2] = {0.f, 0.f};
    const size_t hbase = (size_t)t * BATCH * HDIM;

    for (int k0 = 0; k0 < HDIM; k0 += 32) {
        if (tid < 64) {   // A tile: 8x32 -> 64 float4
            int r  = tid >> 3;
            int c4 = (tid & 7) * 4;
            int rr = r0 + r;
            int bi = rr >> 3;
            float4 h4 = *(const float4*)&g_Hph[hbase + (size_t)bi * HDIM + k0 + c4];
            float4 z4 = ldcg4(&g_Hpz[(size_t)rr * HDIM + k0 + c4]);
            float* dst = &sA[r * 33 + c4];
            dst[0] = fmaxf(h4.x + z4.x, 0.f);
            dst[1] = fmaxf(h4.y + z4.y, 0.f);
            dst[2] = fmaxf(h4.z + z4.z, 0.f);
            dst[3] = fmaxf(h4.w + z4.w, 0.f);
        }
        #pragma unroll
        for (int l = 0; l < 4; l++) {   // W tile: 32x128 -> 1024 float4
            int v  = tid + l * 256;
            int r  = v >> 5;
            int c4 = (v & 31) * 4;
            *(float4*)&sB[r * 132 + c4] =
                *(const float4*)&Wp2[(size_t)(k0 + r) * ZDIM + c4];
        }
        __syncthreads();
        #pragma unroll
        for (int k = 0; k < 32; k++) {
            float a   = sA[ty * 33 + k];
            float bm0 = sB[k * 132 + tx * 2];
            float bm1 = sB[k * 132 + tx * 2 + 1];
            float bl0 = sB[k * 132 + 64 + tx * 2];
            float bl1 = sB[k * 132 + 64 + tx * 2 + 1];
            am[0] = fmaf(a, bm0, am[0]);
            am[1] = fmaf(a, bm1, am[1]);
            al[0] = fmaf(a, bl0, al[0]);
            al[1] = fmaf(a, bl1, al[1]);
        }
        __syncthreads();
    }

    const int rr = r0 + ty;
    const int bi = rr >> 3;
    const float mt = g_Mt[t * BATCH + bi];
    float local = 0.f;
    #pragma unroll
    for (int j = 0; j < 2; j++) {
        int c = tx * 2 + j;
        float mean   = am[j] + bp2[c];
        float logvar = al[j] + bp2[64 + c];
        float x  = X[((size_t)t * BATCH + bi) * DIN + c];
        float dv = x - mean;
        local += mt * 0.5f * (LOG_2PI + logvar + dv * dv * expf(-logvar));
    }
    sh[tid] = local;
    __syncthreads();
    for (int s2 = 128; s2 > 0; s2 >>= 1) {
        if (tid < s2) sh[tid] += sh[tid + s2];
        __syncthreads();
    }
    if (tid == 0) g_reconpart[t * NBLK + b] = sh[0];
    __syncthreads();
}

__global__ void __launch_bounds__(NTHR)
scan_persistent(const float* __restrict__ Wd2, const float* __restrict__ bd2,
                const float* __restrict__ noise,
                const float* __restrict__ Wp1z, const float* __restrict__ Wd1z,
                const float* __restrict__ Wp2, const float* __restrict__ bp2,
                const float* __restrict__ X)
{
    __shared__ float sh[6400];   // 25.6 KB, aliased across phases
    const int b = blockIdx.x;
    const int tid = threadIdx.x;

    // register-resident z slice for phase A (this block's fixed tile)
    const int r0a = (b >> 1) * 16;
    const int c0a = (b & 1) * 64;
    const int tyA = tid >> 4;
    const int txA = tid & 15;
    float4 z4 = ldcg4(&g_z[(size_t)(r0a + tyA) * ZDIM + c0a + txA * 4]);
    float zreg[4] = { z4.x, z4.y, z4.z, z4.w };

    unsigned ls = 0;
    for (int t = 0; t < T_STEPS; t++) {
        phaseA(t, Wd2, bd2, noise, sh, zreg);
        if (t > 0) phaseC(t - 1, Wp2, bp2, X, sh);
        gridbar(ls);                 // z ready for B; Hpz consumed
        phaseB(Wp1z, Wd1z, sh);
        gridbar(ls);                 // Hz/Hpz ready for next A / C
    }
    phaseC(T_STEPS - 1, Wp2, bp2, X, sh);
}

// ---------------- outputs ---------------------------------------------------
__global__ void copy_z(float* __restrict__ out)
{
    int i = blockIdx.x * blockDim.x + threadIdx.x;
    out[i] = g_z[i];
}

__global__ void finalize(float* __restrict__ out, int out_size)
{
    int tid = threadIdx.x;   // 256
    float k = 0.f, r = 0.f;
    for (int i = tid; i < T_STEPS * NBLK; i += 256) k += g_kldpart[i];
    for (int i = tid; i < T_STEPS * NBLK; i += 256) r += g_reconpart[i];
    __shared__ float rk[256], rr[256];
    rk[tid] = k; rr[tid] = r;
    __syncthreads();
    for (int s = 128; s > 0; s >>= 1) {
        if (tid < s) { rk[tid] += rk[tid + s]; rr[tid] += rr[tid + s]; }
        __syncthreads();
    }
    if (tid == 0) {
        float kld   = rk[0] * (0.5f * DT / (float)BS);
        float recon = rr[0] * (1.f / (float)BS);
        out[out_size - 3] = recon + kld;
        out[out_size - 2] = recon;
        out[out_size - 1] = kld;
    }
}

// ---------------- launch ----------------------------------------------------
extern "C" void kernel_launch(void* const* d_in, const int* in_sizes, int n_in,
                              void* d_out, int out_size)
{
    const float* X     = (const float*)d_in[0];
    const float* M     = (const float*)d_in[1];
    const float* cov   = (const float*)d_in[2];
    const float* ph    = (const float*)d_in[3];
    const float* phpos = (const float*)d_in[4];
    const float* noise = (const float*)d_in[5];
    const float* Wc1 = (const float*)d_in[6],  *bc1 = (const float*)d_in[7];
    const float* Wc2 = (const float*)d_in[8],  *bc2 = (const float*)d_in[9];
    const float* Wd1 = (const float*)d_in[10], *bd1 = (const float*)d_in[11];
    const float* Wd2 = (const float*)d_in[12], *bd2 = (const float*)d_in[13];
    const float* Wf1 = (const float*)d_in[14], *bf1 = (const float*)d_in[15];
    const float* Wf2 = (const float*)d_in[16], *bf2 = (const float*)d_in[17];
    const float* Wp1 = (const float*)d_in[18], *bp1 = (const float*)d_in[19];
    const float* Wp2 = (const float*)d_in[20], *bp2 = (const float*)d_in[21];
    float* out = (float*)d_out;

    float *pHh, *pHhpos, *pHph, *pHf, *pdiff, *pz, *pHz;
    cudaGetSymbolAddress((void**)&pHh,    g_Hh);
    cudaGetSymbolAddress((void**)&pHhpos, g_Hhpos);
    cudaGetSymbolAddress((void**)&pHph,   g_Hph);
    cudaGetSymbolAddress((void**)&pHf,    g_Hf);
    cudaGetSymbolAddress((void**)&pdiff,  g_diff);
    cudaGetSymbolAddress((void**)&pz,     g_z);
    cudaGetSymbolAddress((void**)&pHz,    g_Hz);

    // ---- precompute (parallel over all T) ----
    z0_kernel<<<BATCH, 128>>>(cov, Wc1, bc1, Wc2, bc2);
    mt_kernel<<<64, 256>>>(M);
    gemm_f32<0, false><<<dim3(HDIM/64, TB/64), 256>>>(ph,  nullptr, Wd1, bd1, pHh,    TB, HDIM, RDIM);
    gemm_f32<0, true ><<<dim3(HDIM/64, TB/64), 256>>>(ph,  phpos,   Wd1, bd1, pHhpos, TB, HDIM, RDIM);
    gemm_f32<0, false><<<dim3(HDIM/64, TB/64), 256>>>(ph,  nullptr, Wp1, bp1, pHph,   TB, HDIM, RDIM);
    gemm_f32<1, false><<<dim3(HDIM/64, TB/64), 256>>>(ph,  nullptr, Wf1, bf1, pHf,    TB, HDIM, RDIM);
    gemm_f32<2, false><<<dim3(ZDIM/64, TB/64), 256>>>(pHf, nullptr, Wf2, bf2, pdiff,  TB, ZDIM, HDIM);

    // initial Hz = z0 @ Wd1[R:,:]
    gemm_f32<0, false><<<dim3(HDIM/64, BS/64), 256>>>(pz, nullptr, Wd1 + RDIM * HDIM,
                                                      nullptr, pHz, BS, HDIM, ZDIM);

    // ---- persistent scan: entire T loop in ONE kernel ----
    scan_persistent<<<NBLK, NTHR>>>(Wd2, bd2, noise,
                                    Wp1 + RDIM * HDIM, Wd1 + RDIM * HDIM,
                                    Wp2, bp2, X);

    // ---- outputs ----
    copy_z<<<(BS * ZDIM) / 256, 256>>>(out);
    finalize<<<1, 256>>>(out, out_size);
}

// round 4
// speedup vs baseline: 1.4525x; 1.2092x over previous
#include <cuda_runtime.h>
#include <math.h>

#define T_STEPS 128
#define BATCH   128
#define SAMP    8
#define DIN     64
#define RDIM    256
#define ZDIM    128
#define HDIM    512
#define BS      1024   /* BATCH*SAMP */
#define TB      16384  /* T_STEPS*BATCH */
#define NBLK    128
#define NTHR    512

#define DT       0.05f
#define SQRT_DT  0.22360679774997896f
#define LOG_2PI  1.8378770664093453f

// ---------------- scratch (static device globals; no runtime alloc) -------
__device__ __align__(16) float g_Hh[TB * HDIM];
__device__ __align__(16) float g_Hhpos[TB * HDIM];
__device__ __align__(16) float g_Hph[TB * HDIM];
__device__ __align__(16) float g_Hf[TB * HDIM];
__device__ __align__(16) float g_diff[TB * ZDIM];
__device__ __align__(16) float g_Mt[T_STEPS * BATCH];
__device__ __align__(16) float g_z[BS * ZDIM];
__device__ __align__(16) float g_Hz[BS * HDIM];
__device__ __align__(16) float g_Hpz[BS * HDIM];
__device__ float g_kldpart[T_STEPS * NBLK];
__device__ float g_reconpart[T_STEPS * NBLK];

// grid barrier state (all-zero again after an even number of barriers)
__device__ unsigned g_barcnt;
__device__ volatile unsigned g_barsense;

__device__ __forceinline__ float4 ldcg4(const float* p) {
    return __ldcg((const float4*)p);
}
__device__ __forceinline__ float2 ldcg2(const float* p) {
    return __ldcg((const float2*)p);
}

// ---------------- z0: cov -> CH -> Z (relu, tanh) --------------------------
__global__ void z0_kernel(const float* __restrict__ cov,
                          const float* __restrict__ Wc1, const float* __restrict__ bc1,
                          const float* __restrict__ Wc2, const float* __restrict__ bc2)
{
    int b = blockIdx.x;
    int tid = threadIdx.x;  // 128
    __shared__ float sc[32];
    __shared__ float shh[64];
    if (tid < 32) sc[tid] = cov[b * 32 + tid];
    __syncthreads();
    if (tid < 64) {
        float acc = bc1[tid];
        #pragma unroll
        for (int c = 0; c < 32; c++) acc = fmaf(sc[c], Wc1[c * 64 + tid], acc);
        shh[tid] = fmaxf(acc, 0.f);
    }
    __syncthreads();
    float acc = bc2[tid];
    #pragma unroll
    for (int k = 0; k < 64; k++) acc = fmaf(shh[k], Wc2[k * 128 + tid], acc);
    float z = tanhf(acc);
    #pragma unroll
    for (int s = 0; s < SAMP; s++)
        g_z[(b * SAMP + s) * ZDIM + tid] = z;
}

// ---------------- Mt = mean(M, axis=-1) ------------------------------------
__global__ void mt_kernel(const float* __restrict__ M)
{
    int i = blockIdx.x * blockDim.x + threadIdx.x;
    const float4* p = (const float4*)(M + (size_t)i * DIN);
    float s = 0.f;
    #pragma unroll
    for (int j = 0; j < DIN / 4; j++) { float4 v = p[j]; s += v.x + v.y + v.z + v.w; }
    g_Mt[i] = s * (1.f / (float)DIN);
}

// ---------------- generic fp32 tiled GEMM (precompute) ---------------------
template<int ACT, bool SUMA>
__global__ void gemm_f32(const float* __restrict__ A, const float* __restrict__ A2,
                         const float* __restrict__ W, const float* __restrict__ bias,
                         float* __restrict__ C, int M, int N, int K)
{
    __shared__ float sA[64][33];
    __shared__ float sB[32][68];
    const int bm = blockIdx.y * 64;
    const int bn = blockIdx.x * 64;
    const int tid = threadIdx.x;
    const int tx = tid & 15;
    const int ty = tid >> 4;
    float acc[4][4] = {};
    for (int k0 = 0; k0 < K; k0 += 32) {
        #pragma unroll
        for (int l = 0; l < 2; l++) {
            int v  = tid + l * 256;
            int r  = v >> 3;
            int c4 = (v & 7) * 4;
            float4 av = *(const float4*)&A[(size_t)(bm + r) * K + k0 + c4];
            if (SUMA) {
                float4 b4 = *(const float4*)&A2[(size_t)(bm + r) * K + k0 + c4];
                av.x += b4.x; av.y += b4.y; av.z += b4.z; av.w += b4.w;
            }
            sA[r][c4 + 0] = av.x; sA[r][c4 + 1] = av.y;
            sA[r][c4 + 2] = av.z; sA[r][c4 + 3] = av.w;
        }
        #pragma unroll
        for (int l = 0; l < 2; l++) {
            int v  = tid + l * 256;
            int r  = v >> 4;
            int c4 = (v & 15) * 4;
            *(float4*)&sB[r][c4] = *(const float4*)&W[(size_t)(k0 + r) * N + bn + c4];
        }
        __syncthreads();
        #pragma unroll
        for (int k = 0; k < 32; k++) {
            float a[4];
            #pragma unroll
            for (int i = 0; i < 4; i++) a[i] = sA[ty * 4 + i][k];
            float4 bv = *(const float4*)&sB[k][tx * 4];
            #pragma unroll
            for (int i = 0; i < 4; i++) {
                acc[i][0] = fmaf(a[i], bv.x, acc[i][0]);
                acc[i][1] = fmaf(a[i], bv.y, acc[i][1]);
                acc[i][2] = fmaf(a[i], bv.z, acc[i][2]);
                acc[i][3] = fmaf(a[i], bv.w, acc[i][3]);
            }
        }
        __syncthreads();
    }
    #pragma unroll
    for (int i = 0; i < 4; i++) {
        int r = bm + ty * 4 + i;
        #pragma unroll
        for (int j = 0; j < 4; j++) {
            int c = bn + tx * 4 + j;
            float v = acc[i][j] + (bias ? bias[c] : 0.f);
            if (ACT == 1) v = fmaxf(v, 0.f);
            if (ACT == 2) v = expf(v);
            C[(size_t)r * N + c] = v;
        }
    }
}

// ================= persistent scan kernel (512 threads) ====================

__device__ __forceinline__ void gridbar(unsigned& ls)
{
    ls ^= 1u;
    __syncthreads();
    if (threadIdx.x == 0) {
        __threadfence();
        if (atomicAdd(&g_barcnt, 1u) == NBLK - 1) {
            g_barcnt = 0;
            __threadfence();
            g_barsense = ls;
        } else {
            while (g_barsense != ls) __nanosleep(32);
            __threadfence();
        }
    }
    __syncthreads();
}

// smem layout offsets (floats)
#define A_SAP   0            /* [16][68]  phaseA p-tile  */
#define A_SAQ   1088         /* [16][68]  phaseA q-tile  */
#define A_SB    2176         /* [64][68]  phaseA B-tile  */
#define A_RED   6528         /* [512]                     */
#define B_SA    0            /* [64][36]  phaseB A-tile  */
#define B_SB    2304         /* [32][132] phaseB B-tile  */
#define C_SA    0            /* [2][8][36]                */
#define C_SB    576          /* [2][32][132]              */
#define C_EXCH  9024         /* [256][4]                  */
#define C_RED   10048        /* [512]                     */
#define SH_TOT  10752

// Phase A: drift dual GEMM + Euler-Maruyama z update + KLD partial.
// Block b: rows (b>>1)*16..+16 (warp=row), cols (b&1)*64..+64 (lane=2 cols).
__device__ void phaseA(int t, const float* __restrict__ Wd2,
                       const float* __restrict__ bd2,
                       const float* __restrict__ noise,
                       float* sh, float zreg[2], int rowA, int colA)
{
    const int tid = threadIdx.x;
    const int w = tid >> 5;
    const int lane = tid & 31;
    const int r0 = (blockIdx.x >> 1) * 16;
    const int c0 = (blockIdx.x & 1) * 64;
    float p0 = 0.f, p1 = 0.f, q0 = 0.f, q1 = 0.f;
    const size_t hbase = (size_t)t * BATCH * HDIM;

    for (int k0 = 0; k0 < HDIM; k0 += 64) {
        __syncthreads();
        {   // A tiles: Ap (tid<256) / Aq (tid>=256): 16 rows x 64 k
            int v  = tid & 255;
            int r  = v >> 4;
            int c4 = (v & 15) * 4;
            int rr = r0 + r;
            int bi = rr >> 3;
            float4 z4 = ldcg4(&g_Hz[(size_t)rr * HDIM + k0 + c4]);
            const float* hsrc = (tid < 256) ? g_Hh : g_Hhpos;
            float4 h4 = *(const float4*)&hsrc[hbase + (size_t)bi * HDIM + k0 + c4];
            float* d = sh + ((tid < 256) ? A_SAP : A_SAQ) + r * 68 + c4;
            d[0] = fmaxf(h4.x + z4.x, 0.f);
            d[1] = fmaxf(h4.y + z4.y, 0.f);
            d[2] = fmaxf(h4.z + z4.z, 0.f);
            d[3] = fmaxf(h4.w + z4.w, 0.f);
        }
        #pragma unroll
        for (int l = 0; l < 2; l++) {   // B: 64 k x 64 cols = 1024 float4
            int v  = tid + l * 512;
            int r  = v >> 4;
            int c4 = (v & 15) * 4;
            *(float4*)&sh[A_SB + r * 68 + c4] =
                *(const float4*)&Wd2[(size_t)(k0 + r) * ZDIM + c0 + c4];
        }
        __syncthreads();
        const float* ap = sh + A_SAP + w * 68;
        const float* aq = sh + A_SAQ + w * 68;
        const float* bb = sh + A_SB + lane * 2;
        #pragma unroll
        for (int k = 0; k < 64; k++) {
            float a1 = ap[k], a2 = aq[k];
            float2 bv = *(const float2*)&bb[k * 68];
            p0 = fmaf(a1, bv.x, p0);
            p1 = fmaf(a1, bv.y, p1);
            q0 = fmaf(a2, bv.x, q0);
            q1 = fmaf(a2, bv.y, q1);
        }
    }

    // epilogue
    const int bi = rowA >> 3;
    const int si = rowA & 7;
    const float* drow = &g_diff[((size_t)t * BATCH + bi) * ZDIM];
    const float* nrow = &noise[(((size_t)t * BATCH + bi) * SAMP + si) * ZDIM];
    float b0 = bd2[colA], b1 = bd2[colA + 1];
    float pr0 = 0.1f * tanhf(p0 + b0);
    float po0 = 0.1f * tanhf(q0 + b0);
    float pr1 = 0.1f * tanhf(p1 + b1);
    float po1 = 0.1f * tanhf(q1 + b1);
    float d0 = drow[colA], d1 = drow[colA + 1];
    float e0 = nrow[colA], e1 = nrow[colA + 1];
    zreg[0] += DT * po0 + SQRT_DT * d0 * e0;
    zreg[1] += DT * po1 + SQRT_DT * d1 * e1;
    __stcg((float2*)&g_z[(size_t)rowA * ZDIM + colA], make_float2(zreg[0], zreg[1]));
    float er0 = (pr0 - po0) / d0;
    float er1 = (pr1 - po1) / d1;
    float kl = fmaf(er0, er0, er1 * er1);

    float* red = sh + A_RED;
    red[tid] = kl;
    __syncthreads();
    for (int s2 = 256; s2 > 0; s2 >>= 1) {
        if (tid < s2) red[tid] += red[tid + s2];
        __syncthreads();
    }
    if (tid == 0) g_kldpart[t * NBLK + blockIdx.x] = red[0];
}

// Phase B: Hpz = z@Wp1z, Hz = z@Wd1z. mat=b>>6, tile 64x128, K=128.
__device__ void phaseB(const float* __restrict__ Wp1z,
                       const float* __restrict__ Wd1z, float* sh)
{
    const int b = blockIdx.x;
    const int mat = b >> 6;
    const float* __restrict__ W = mat ? Wd1z : Wp1z;
    float* __restrict__ C = mat ? g_Hz : g_Hpz;
    const int idx = b & 63;
    const int r0 = (idx >> 2) * 64;
    const int c0 = (idx & 3) * 128;
    const int tid = threadIdx.x;
    const int ty = tid >> 5;   // 16 row groups of 4
    const int lane = tid & 31; // col quad
    float acc[4][4] = {};

    for (int k0 = 0; k0 < ZDIM; k0 += 32) {
        __syncthreads();
        {   // A: 64 rows x 32 k = 512 float4
            int r  = tid >> 3;
            int c4 = (tid & 7) * 4;
            float4 z4 = ldcg4(&g_z[(size_t)(r0 + r) * ZDIM + k0 + c4]);
            *(float4*)&sh[B_SA + r * 36 + c4] = z4;
        }
        #pragma unroll
        for (int l = 0; l < 2; l++) {   // B: 32 k x 128 cols = 1024 float4
            int v  = tid + l * 512;
            int r  = v >> 5;
            int c4 = (v & 31) * 4;
            *(float4*)&sh[B_SB + r * 132 + c4] =
                *(const float4*)&W[(size_t)(k0 + r) * HDIM + c0 + c4];
        }
        __syncthreads();
        const float* sa = sh + B_SA + ty * 4 * 36;
        const float* bb = sh + B_SB + lane * 4;
        #pragma unroll
        for (int k = 0; k < 32; k++) {
            float4 bv = *(const float4*)&bb[k * 132];
            #pragma unroll
            for (int i = 0; i < 4; i++) {
                float a = sa[i * 36 + k];
                acc[i][0] = fmaf(a, bv.x, acc[i][0]);
                acc[i][1] = fmaf(a, bv.y, acc[i][1]);
                acc[i][2] = fmaf(a, bv.z, acc[i][2]);
                acc[i][3] = fmaf(a, bv.w, acc[i][3]);
            }
        }
    }
    #pragma unroll
    for (int i = 0; i < 4; i++)
        __stcg((float4*)&C[(size_t)(r0 + ty * 4 + i) * HDIM + c0 + lane * 4],
               make_float4(acc[i][0], acc[i][1], acc[i][2], acc[i][3]));
}

// Phase C: p head + recon partial, K split across thread halves.
// Block b: rows b*8..+8. Each half computes full 8x(64 mean + 64 logvar)
// partials over its 256-k range; halves combined through smem.
__device__ void phaseC(int t, const float* __restrict__ Wp2,
                       const float* __restrict__ bp2,
                       const float* __restrict__ X, float* sh)
{
    const int b = blockIdx.x;
    const int r0 = b * 8;
    const int tid = threadIdx.x;
    const int h = tid >> 8;          // k half
    const int th = tid & 255;
    const int wh = th >> 5;
    const int lane = th & 31;
    const int rl = (wh & 3) * 2 + (lane >> 4);        // local row 0..7
    const int cp = (wh >> 2) * 32 + (lane & 15) * 2;  // mean col 0..62
    float am0 = 0.f, am1 = 0.f, al0 = 0.f, al1 = 0.f;
    const size_t hbase = (size_t)t * BATCH * HDIM;
    float* sAh = sh + C_SA + h * (8 * 36);
    float* sBh = sh + C_SB + h * (32 * 132);
    const int kbase = h * 256;

    for (int c8 = 0; c8 < 8; c8++) {
        const int k0 = kbase + c8 * 32;
        __syncthreads();
        if (th < 64) {   // A: 8 rows x 32 k = 64 float4 per half
            int r  = th >> 3;
            int c4 = (th & 7) * 4;
            int rr = r0 + r;
            int bi = rr >> 3;
            float4 h4 = *(const float4*)&g_Hph[hbase + (size_t)bi * HDIM + k0 + c4];
            float4 z4 = ldcg4(&g_Hpz[(size_t)rr * HDIM + k0 + c4]);
            float* d = &sAh[r * 36 + c4];
            d[0] = fmaxf(h4.x + z4.x, 0.f);
            d[1] = fmaxf(h4.y + z4.y, 0.f);
            d[2] = fmaxf(h4.z + z4.z, 0.f);
            d[3] = fmaxf(h4.w + z4.w, 0.f);
        }
        #pragma unroll
        for (int l = 0; l < 4; l++) {   // B: 32 k x 128 cols = 1024 float4 per half
            int v  = th + l * 256;
            int r  = v >> 5;
            int c4 = (v & 31) * 4;
            *(float4*)&sBh[r * 132 + c4] =
                *(const float4*)&Wp2[(size_t)(k0 + r) * ZDIM + c4];
        }
        __syncthreads();
        const float* sa = &sAh[rl * 36];
        const float* bm = &sBh[cp];
        const float* bl = &sBh[64 + cp];
        #pragma unroll
        for (int k = 0; k < 32; k++) {
            float a = sa[k];
            float2 m2 = *(const float2*)&bm[k * 132];
            float2 l2 = *(const float2*)&bl[k * 132];
            am0 = fmaf(a, m2.x, am0);
            am1 = fmaf(a, m2.y, am1);
            al0 = fmaf(a, l2.x, al0);
            al1 = fmaf(a, l2.y, al1);
        }
    }

    // combine halves + NLL epilogue
    __syncthreads();
    if (h == 1) {
        float* e = &sh[C_EXCH + th * 4];
        e[0] = am0; e[1] = am1; e[2] = al0; e[3] = al1;
    }
    __syncthreads();
    float local = 0.f;
    if (h == 0) {
        const float* e = &sh[C_EXCH + th * 4];
        am0 += e[0]; am1 += e[1]; al0 += e[2]; al1 += e[3];
        int row = r0 + rl;
        int bi = row >> 3;
        float mt = g_Mt[t * BATCH + bi];
        const float* xr = &X[((size_t)t * BATCH + bi) * DIN];
        float mean0 = am0 + bp2[cp];
        float lv0   = al0 + bp2[64 + cp];
        float dv0 = xr[cp] - mean0;
        local += mt * 0.5f * (LOG_2PI + lv0 + dv0 * dv0 * expf(-lv0));
        float mean1 = am1 + bp2[cp + 1];
        float lv1   = al1 + bp2[64 + cp + 1];
        float dv1 = xr[cp + 1] - mean1;
        local += mt * 0.5f * (LOG_2PI + lv1 + dv1 * dv1 * expf(-lv1));
    }
    float* red = sh + C_RED;
    red[tid] = local;
    __syncthreads();
    for (int s2 = 256; s2 > 0; s2 >>= 1) {
        if (tid < s2) red[tid] += red[tid + s2];
        __syncthreads();
    }
    if (tid == 0) g_reconpart[t * NBLK + b] = red[0];
}

__global__ void __launch_bounds__(NTHR, 1)
scan_persistent(const float* __restrict__ Wd2, const float* __restrict__ bd2,
                const float* __restrict__ noise,
                const float* __restrict__ Wp1z, const float* __restrict__ Wd1z,
                const float* __restrict__ Wp2, const float* __restrict__ bp2,
                const float* __restrict__ X)
{
    __shared__ float sh[SH_TOT];   // 43 KB, aliased across phases
    const int tid = threadIdx.x;
    const int rowA = ((blockIdx.x >> 1) * 16) + (tid >> 5);
    const int colA = ((blockIdx.x & 1) * 64) + (tid & 31) * 2;

    // register-resident z slice for phase A (this block's fixed tile)
    float2 z2 = ldcg2(&g_z[(size_t)rowA * ZDIM + colA]);
    float zreg[2] = { z2.x, z2.y };

    unsigned ls = 0;
    for (int t = 0; t < T_STEPS; t++) {
        phaseA(t, Wd2, bd2, noise, sh, zreg, rowA, colA);
        if (t > 0) phaseC(t - 1, Wp2, bp2, X, sh);
        gridbar(ls);                 // z(t+1) ready; Hpz(t-1) consumed
        phaseB(Wp1z, Wd1z, sh);      // Hz(t+1), Hpz(t)
        gridbar(ls);
    }
    phaseC(T_STEPS - 1, Wp2, bp2, X, sh);
}

// ---------------- outputs ---------------------------------------------------
__global__ void copy_z(float* __restrict__ out)
{
    int i = blockIdx.x * blockDim.x + threadIdx.x;
    out[i] = g_z[i];
}

__global__ void finalize(float* __restrict__ out, int out_size)
{
    int tid = threadIdx.x;   // 256
    float k = 0.f, r = 0.f;
    for (int i = tid; i < T_STEPS * NBLK; i += 256) k += g_kldpart[i];
    for (int i = tid; i < T_STEPS * NBLK; i += 256) r += g_reconpart[i];
    __shared__ float rk[256], rr[256];
    rk[tid] = k; rr[tid] = r;
    __syncthreads();
    for (int s = 128; s > 0; s >>= 1) {
        if (tid < s) { rk[tid] += rk[tid + s]; rr[tid] += rr[tid + s]; }
        __syncthreads();
    }
    if (tid == 0) {
        float kld   = rk[0] * (0.5f * DT / (float)BS);
        float recon = rr[0] * (1.f / (float)BS);
        out[out_size - 3] = recon + kld;
        out[out_size - 2] = recon;
        out[out_size - 1] = kld;
    }
}

// ---------------- launch ----------------------------------------------------
extern "C" void kernel_launch(void* const* d_in, const int* in_sizes, int n_in,
                              void* d_out, int out_size)
{
    const float* X     = (const float*)d_in[0];
    const float* M     = (const float*)d_in[1];
    const float* cov   = (const float*)d_in[2];
    const float* ph    = (const float*)d_in[3];
    const float* phpos = (const float*)d_in[4];
    const float* noise = (const float*)d_in[5];
    const float* Wc1 = (const float*)d_in[6],  *bc1 = (const float*)d_in[7];
    const float* Wc2 = (const float*)d_in[8],  *bc2 = (const float*)d_in[9];
    const float* Wd1 = (const float*)d_in[10], *bd1 = (const float*)d_in[11];
    const float* Wd2 = (const float*)d_in[12], *bd2 = (const float*)d_in[13];
    const float* Wf1 = (const float*)d_in[14], *bf1 = (const float*)d_in[15];
    const float* Wf2 = (const float*)d_in[16], *bf2 = (const float*)d_in[17];
    const float* Wp1 = (const float*)d_in[18], *bp1 = (const float*)d_in[19];
    const float* Wp2 = (const float*)d_in[20], *bp2 = (const float*)d_in[21];
    float* out = (float*)d_out;

    float *pHh, *pHhpos, *pHph, *pHf, *pdiff, *pz, *pHz;
    cudaGetSymbolAddress((void**)&pHh,    g_Hh);
    cudaGetSymbolAddress((void**)&pHhpos, g_Hhpos);
    cudaGetSymbolAddress((void**)&pHph,   g_Hph);
    cudaGetSymbolAddress((void**)&pHf,    g_Hf);
    cudaGetSymbolAddress((void**)&pdiff,  g_diff);
    cudaGetSymbolAddress((void**)&pz,     g_z);
    cudaGetSymbolAddress((void**)&pHz,    g_Hz);

    // ---- precompute (parallel over all T) ----
    z0_kernel<<<BATCH, 128>>>(cov, Wc1, bc1, Wc2, bc2);
    mt_kernel<<<64, 256>>>(M);
    gemm_f32<0, false><<<dim3(HDIM/64, TB/64), 256>>>(ph,  nullptr, Wd1, bd1, pHh,    TB, HDIM, RDIM);
    gemm_f32<0, true ><<<dim3(HDIM/64, TB/64), 256>>>(ph,  phpos,   Wd1, bd1, pHhpos, TB, HDIM, RDIM);
    gemm_f32<0, false><<<dim3(HDIM/64, TB/64), 256>>>(ph,  nullptr, Wp1, bp1, pHph,   TB, HDIM, RDIM);
    gemm_f32<1, false><<<dim3(HDIM/64, TB/64), 256>>>(ph,  nullptr, Wf1, bf1, pHf,    TB, HDIM, RDIM);
    gemm_f32<2, false><<<dim3(ZDIM/64, TB/64), 256>>>(pHf, nullptr, Wf2, bf2, pdiff,  TB, ZDIM, HDIM);

    // initial Hz = z0 @ Wd1[R:,:]
    gemm_f32<0, false><<<dim3(HDIM/64, BS/64), 256>>>(pz, nullptr, Wd1 + RDIM * HDIM,
                                                      nullptr, pHz, BS, HDIM, ZDIM);

    // ---- persistent scan: entire T loop in ONE kernel ----
    scan_persistent<<<NBLK, NTHR>>>(Wd2, bd2, noise,
                                    Wp1 + RDIM * HDIM, Wd1 + RDIM * HDIM,
                                    Wp2, bp2, X);

    // ---- outputs ----
    copy_z<<<(BS * ZDIM) / 256, 256>>>(out);
    finalize<<<1, 256>>>(out, out_size);
}

// round 5
// speedup vs baseline: 2.3519x; 1.6192x over previous
#include <cuda_runtime.h>
#include <math.h>
#include <stdint.h>

#define T_STEPS 128
#define BATCH   128
#define SAMP    8
#define DIN     64
#define RDIM    256
#define ZDIM    128
#define HDIM    512
#define BS      1024
#define TB      16384
#define NBLK    128
#define NTHR    512

#define DT       0.05f
#define SQRT_DT  0.22360679774997896f
#define LOG_2PI  1.8378770664093453f

// ---------------- scratch ---------------------------------------------------
__device__ __align__(16) float g_Hh[TB * HDIM];
__device__ __align__(16) float g_Hhpos[TB * HDIM];
__device__ __align__(16) float g_Hph[TB * HDIM];
__device__ __align__(16) float g_Hf[TB * HDIM];
__device__ __align__(16) float g_diff[TB * ZDIM];
__device__ __align__(16) float g_Mt[T_STEPS * BATCH];
__device__ __align__(16) float g_z[BS * ZDIM];
__device__ __align__(16) float g_Hz[BS * HDIM];
__device__ __align__(16) float g_Hpz[BS * HDIM];
// tf32-preconverted weights (bits stored in float)
__device__ __align__(16) float g_Wd2t[HDIM * ZDIM];
__device__ __align__(16) float g_Wp1zt[ZDIM * HDIM];
__device__ __align__(16) float g_Wd1zt[ZDIM * HDIM];
__device__ __align__(16) float g_Wp2t[HDIM * ZDIM];
__device__ float g_kldpart[T_STEPS * 64];
__device__ float g_reconpart[T_STEPS * 64];

__device__ unsigned g_barcnt;
__device__ volatile unsigned g_barsense;

__device__ __forceinline__ float4 ldcg4(const float* p) { return __ldcg((const float4*)p); }
__device__ __forceinline__ float2 ldcg2(const float* p) { return __ldcg((const float2*)p); }
__device__ __forceinline__ unsigned f2tf(float f) {
    unsigned r; asm("cvt.rna.tf32.f32 %0, %1;" : "=r"(r) : "f"(f)); return r;
}
#define FU(x) __float_as_uint(x)

__device__ __forceinline__ void mma8(float c[4], const unsigned a[4],
                                     unsigned b0, unsigned b1)
{
    asm volatile(
        "mma.sync.aligned.m16n8k8.row.col.f32.tf32.tf32.f32 "
        "{%0,%1,%2,%3}, {%4,%5,%6,%7}, {%8,%9}, {%0,%1,%2,%3};"
        : "+f"(c[0]), "+f"(c[1]), "+f"(c[2]), "+f"(c[3])
        : "r"(a[0]), "r"(a[1]), "r"(a[2]), "r"(a[3]), "r"(b0), "r"(b1));
}

// ---------------- z0 --------------------------------------------------------
__global__ void z0_kernel(const float* __restrict__ cov,
                          const float* __restrict__ Wc1, const float* __restrict__ bc1,
                          const float* __restrict__ Wc2, const float* __restrict__ bc2)
{
    int b = blockIdx.x;
    int tid = threadIdx.x;  // 128
    __shared__ float sc[32];
    __shared__ float shh[64];
    if (tid < 32) sc[tid] = cov[b * 32 + tid];
    __syncthreads();
    if (tid < 64) {
        float acc = bc1[tid];
        #pragma unroll
        for (int c = 0; c < 32; c++) acc = fmaf(sc[c], Wc1[c * 64 + tid], acc);
        shh[tid] = fmaxf(acc, 0.f);
    }
    __syncthreads();
    float acc = bc2[tid];
    #pragma unroll
    for (int k = 0; k < 64; k++) acc = fmaf(shh[k], Wc2[k * 128 + tid], acc);
    float z = tanhf(acc);
    #pragma unroll
    for (int s = 0; s < SAMP; s++)
        g_z[(b * SAMP + s) * ZDIM + tid] = z;
}

// ---------------- Mt --------------------------------------------------------
__global__ void mt_kernel(const float* __restrict__ M)
{
    int i = blockIdx.x * blockDim.x + threadIdx.x;
    const float4* p = (const float4*)(M + (size_t)i * DIN);
    float s = 0.f;
    #pragma unroll
    for (int j = 0; j < DIN / 4; j++) { float4 v = p[j]; s += v.x + v.y + v.z + v.w; }
    g_Mt[i] = s * (1.f / (float)DIN);
}

// ---------------- weight tf32 pre-conversion --------------------------------
__global__ void cvt_weights(const float* __restrict__ Wd2, const float* __restrict__ Wp1,
                            const float* __restrict__ Wd1, const float* __restrict__ Wp2)
{
    int i = blockIdx.x * 256 + threadIdx.x;   // 65536 each
    g_Wd2t[i]  = __uint_as_float(f2tf(Wd2[i]));
    g_Wp1zt[i] = __uint_as_float(f2tf(Wp1[RDIM * HDIM + i]));
    g_Wd1zt[i] = __uint_as_float(f2tf(Wd1[RDIM * HDIM + i]));
    g_Wp2t[i]  = __uint_as_float(f2tf(Wp2[i]));
}

// ---------------- generic fp32 GEMM (precompute only) ----------------------
template<int ACT, bool SUMA>
__global__ void gemm_f32(const float* __restrict__ A, const float* __restrict__ A2,
                         const float* __restrict__ W, const float* __restrict__ bias,
                         float* __restrict__ C, int M, int N, int K)
{
    __shared__ float sA[64][33];
    __shared__ float sB[32][68];
    const int bm = blockIdx.y * 64;
    const int bn = blockIdx.x * 64;
    const int tid = threadIdx.x;
    const int tx = tid & 15;
    const int ty = tid >> 4;
    float acc[4][4] = {};
    for (int k0 = 0; k0 < K; k0 += 32) {
        #pragma unroll
        for (int l = 0; l < 2; l++) {
            int v  = tid + l * 256;
            int r  = v >> 3;
            int c4 = (v & 7) * 4;
            float4 av = *(const float4*)&A[(size_t)(bm + r) * K + k0 + c4];
            if (SUMA) {
                float4 b4 = *(const float4*)&A2[(size_t)(bm + r) * K + k0 + c4];
                av.x += b4.x; av.y += b4.y; av.z += b4.z; av.w += b4.w;
            }
            sA[r][c4 + 0] = av.x; sA[r][c4 + 1] = av.y;
            sA[r][c4 + 2] = av.z; sA[r][c4 + 3] = av.w;
        }
        #pragma unroll
        for (int l = 0; l < 2; l++) {
            int v  = tid + l * 256;
            int r  = v >> 4;
            int c4 = (v & 15) * 4;
            *(float4*)&sB[r][c4] = *(const float4*)&W[(size_t)(k0 + r) * N + bn + c4];
        }
        __syncthreads();
        #pragma unroll
        for (int k = 0; k < 32; k++) {
            float a[4];
            #pragma unroll
            for (int i = 0; i < 4; i++) a[i] = sA[ty * 4 + i][k];
            float4 bv = *(const float4*)&sB[k][tx * 4];
            #pragma unroll
            for (int i = 0; i < 4; i++) {
                acc[i][0] = fmaf(a[i], bv.x, acc[i][0]);
                acc[i][1] = fmaf(a[i], bv.y, acc[i][1]);
                acc[i][2] = fmaf(a[i], bv.z, acc[i][2]);
                acc[i][3] = fmaf(a[i], bv.w, acc[i][3]);
            }
        }
        __syncthreads();
    }
    #pragma unroll
    for (int i = 0; i < 4; i++) {
        int r = bm + ty * 4 + i;
        #pragma unroll
        for (int j = 0; j < 4; j++) {
            int c = bn + tx * 4 + j;
            float v = acc[i][j] + (bias ? bias[c] : 0.f);
            if (ACT == 1) v = fmaxf(v, 0.f);
            if (ACT == 2) v = expf(v);
            C[(size_t)r * N + c] = v;
        }
    }
}

// ================= persistent tf32 scan kernel ==============================

__device__ __forceinline__ void gridbar(unsigned& ls)
{
    ls ^= 1u;
    __syncthreads();
    if (threadIdx.x == 0) {
        __threadfence();
        if (atomicAdd(&g_barcnt, 1u) == NBLK - 1) {
            g_barcnt = 0;
            __threadfence();
            g_barsense = ls;
        } else {
            while (g_barsense != ls) __nanosleep(32);
            __threadfence();
        }
    }
    __syncthreads();
}

// smem float offsets
#define G1_AP   0        /* [16][36] */
#define G1_AQ   576      /* [16][36] */
#define G1_B    1152     /* [32][136] */
#define G1_QX   0        /* [16][132] post-loop */
#define G2_A    0        /* [64][36] */
#define G2_B    2304     /* [32][136] */
#define G3_A    0        /* [16][36] */
#define G3_B    1152     /* [32][136] */
#define G3_LV   0        /* [16][68] post-loop */
#define RED_OFF 4096     /* [512] */
#define SH_TOTAL 6656

// ---- G1: drift dual GEMM (tf32 MMA) + z update + KLD (blocks 0..63) -------
__device__ void g1_step(int t, const float* __restrict__ bd2,
                        const float* __restrict__ noise, float* sh, float zr[8])
{
    const int tid = threadIdx.x;
    const int w = tid >> 5, lane = tid & 31, g = lane >> 2, tig = lane & 3;
    const int bb = blockIdx.x;
    const int r0 = bb * 16;
    const int isp = (w < 8);
    const int n0 = (w & 7) * 16;
    float acc0[4] = {0.f,0.f,0.f,0.f}, acc1[4] = {0.f,0.f,0.f,0.f};
    const size_t hb = (size_t)t * BATCH * HDIM;

    const float* pA = sh + (isp ? G1_AP : G1_AQ) + g * 36 + tig;
    const float* pB = sh + G1_B + tig * 136 + n0 + g;

    for (int k0 = 0; k0 < HDIM; k0 += 32) {
        __syncthreads();
        if (tid < 256) {   // A staging: p (tid<128) / q (tid 128..255)
            int v  = tid & 127;
            int r  = v >> 3;
            int c4 = (v & 7) * 4;
            int rr = r0 + r, bi = rr >> 3;
            const float* hs = (tid < 128) ? g_Hh : g_Hhpos;
            float4 h4 = *(const float4*)&hs[hb + (size_t)bi * HDIM + k0 + c4];
            float4 z4 = ldcg4(&g_Hz[(size_t)rr * HDIM + k0 + c4]);
            uint4 u;
            u.x = f2tf(fmaxf(h4.x + z4.x, 0.f));
            u.y = f2tf(fmaxf(h4.y + z4.y, 0.f));
            u.z = f2tf(fmaxf(h4.z + z4.z, 0.f));
            u.w = f2tf(fmaxf(h4.w + z4.w, 0.f));
            *(uint4*)&sh[((tid < 128) ? G1_AP : G1_AQ) + r * 36 + c4] = u;
        }
        #pragma unroll
        for (int l = 0; l < 2; l++) {   // B staging: 32x128 tf32 (preconverted)
            int v  = tid + l * 512;
            int r  = v >> 5;
            int c4 = (v & 31) * 4;
            *(uint4*)&sh[G1_B + r * 136 + c4] =
                *(const uint4*)&g_Wd2t[(size_t)(k0 + r) * ZDIM + c4];
        }
        __syncthreads();
        #pragma unroll
        for (int kk = 0; kk < 4; kk++) {
            unsigned a[4] = { FU(pA[kk*8]), FU(pA[kk*8 + 288]),
                              FU(pA[kk*8 + 4]), FU(pA[kk*8 + 292]) };
            unsigned b0a = FU(pB[kk*8*136]);
            unsigned b0b = FU(pB[(kk*8 + 4)*136]);
            unsigned b1a = FU(pB[kk*8*136 + 8]);
            unsigned b1b = FU(pB[(kk*8 + 4)*136 + 8]);
            mma8(acc0, a, b0a, b0b);
            mma8(acc1, a, b1a, b1b);
        }
    }
    __syncthreads();
    if (!isp) {   // q warps export fragments
        #pragma unroll
        for (int nt = 0; nt < 2; nt++) {
            const float* an = nt ? acc1 : acc0;
            int cb = n0 + nt * 8 + 2 * tig;
            *(float2*)&sh[G1_QX + g * 132 + cb]       = make_float2(an[0], an[1]);
            *(float2*)&sh[G1_QX + (g + 8) * 132 + cb] = make_float2(an[2], an[3]);
        }
    }
    __syncthreads();
    float kl = 0.f;
    if (isp) {
        #pragma unroll
        for (int nt = 0; nt < 2; nt++) {
            const float* an = nt ? acc1 : acc0;
            int cb = n0 + nt * 8 + 2 * tig;
            float2 bia = *(const float2*)&bd2[cb];
            #pragma unroll
            for (int rh = 0; rh < 2; rh++) {
                int row = r0 + g + rh * 8;
                int bi = row >> 3, si = row & 7;
                float2 qv = *(float2*)&sh[G1_QX + (g + rh * 8) * 132 + cb];
                float pr0 = 0.1f * tanhf(an[rh*2]     + bia.x);
                float pr1 = 0.1f * tanhf(an[rh*2 + 1] + bia.y);
                float po0 = 0.1f * tanhf(qv.x + bia.x);
                float po1 = 0.1f * tanhf(qv.y + bia.y);
                float2 dv = *(const float2*)&g_diff[((size_t)t * BATCH + bi) * ZDIM + cb];
                float2 ev = *(const float2*)&noise[(((size_t)t * BATCH + bi) * SAMP + si) * ZDIM + cb];
                int zi = nt * 4 + rh * 2;
                zr[zi]     += DT * po0 + SQRT_DT * dv.x * ev.x;
                zr[zi + 1] += DT * po1 + SQRT_DT * dv.y * ev.y;
                __stcg((float2*)&g_z[(size_t)row * ZDIM + cb],
                       make_float2(zr[zi], zr[zi + 1]));
                float e0 = (pr0 - po0) / dv.x;
                float e1 = (pr1 - po1) / dv.y;
                kl += e0 * e0 + e1 * e1;
            }
        }
    }
    float* red = sh + RED_OFF;
    red[tid] = kl;
    __syncthreads();
    for (int s = 256; s > 0; s >>= 1) {
        if (tid < s) red[tid] += red[tid + s];
        __syncthreads();
    }
    if (tid == 0) g_kldpart[t * 64 + bb] = red[0];
    __syncthreads();
}

// ---- G3: p head (tf32 MMA) + NLL (blocks 64..127) --------------------------
__device__ void g3_step(int tc, const float* __restrict__ bp2,
                        const float* __restrict__ X, float* sh)
{
    const int tid = threadIdx.x;
    const int w = tid >> 5, lane = tid & 31, g = lane >> 2, tig = lane & 3;
    const int bb2 = blockIdx.x - 64;
    const int r0 = bb2 * 16;
    const int n0 = w * 8;
    float acc[4] = {0.f,0.f,0.f,0.f};
    const size_t hb = (size_t)tc * BATCH * HDIM;

    const float* pA = sh + G3_A + g * 36 + tig;
    const float* pB = sh + G3_B + tig * 136 + n0 + g;

    for (int k0 = 0; k0 < HDIM; k0 += 32) {
        __syncthreads();
        if (tid < 128) {
            int r  = tid >> 3;
            int c4 = (tid & 7) * 4;
            int rr = r0 + r, bi = rr >> 3;
            float4 h4 = *(const float4*)&g_Hph[hb + (size_t)bi * HDIM + k0 + c4];
            float4 z4 = ldcg4(&g_Hpz[(size_t)rr * HDIM + k0 + c4]);
            uint4 u;
            u.x = f2tf(fmaxf(h4.x + z4.x, 0.f));
            u.y = f2tf(fmaxf(h4.y + z4.y, 0.f));
            u.z = f2tf(fmaxf(h4.z + z4.z, 0.f));
            u.w = f2tf(fmaxf(h4.w + z4.w, 0.f));
            *(uint4*)&sh[G3_A + r * 36 + c4] = u;
        }
        #pragma unroll
        for (int l = 0; l < 2; l++) {
            int v  = tid + l * 512;
            int r  = v >> 5;
            int c4 = (v & 31) * 4;
            *(uint4*)&sh[G3_B + r * 136 + c4] =
                *(const uint4*)&g_Wp2t[(size_t)(k0 + r) * ZDIM + c4];
        }
        __syncthreads();
        #pragma unroll
        for (int kk = 0; kk < 4; kk++) {
            unsigned a[4] = { FU(pA[kk*8]), FU(pA[kk*8 + 288]),
                              FU(pA[kk*8 + 4]), FU(pA[kk*8 + 292]) };
            unsigned b0 = FU(pB[kk*8*136]);
            unsigned b1 = FU(pB[(kk*8 + 4)*136]);
            mma8(acc, a, b0, b1);
        }
    }
    __syncthreads();
    if (w >= 8) {   // logvar warps: export (acc + bias)
        int cb = (n0 - 64) + 2 * tig;
        float2 bia = *(const float2*)&bp2[n0 + 2 * tig];
        *(float2*)&sh[G3_LV + g * 68 + cb]       = make_float2(acc[0] + bia.x, acc[1] + bia.y);
        *(float2*)&sh[G3_LV + (g + 8) * 68 + cb] = make_float2(acc[2] + bia.x, acc[3] + bia.y);
    }
    __syncthreads();
    float local = 0.f;
    if (w < 8) {
        int mc = n0 + 2 * tig;
        float2 bia = *(const float2*)&bp2[mc];
        #pragma unroll
        for (int rh = 0; rh < 2; rh++) {
            int row = r0 + g + rh * 8;
            int bi = row >> 3;
            float mt = g_Mt[tc * BATCH + bi];
            float2 lv = *(float2*)&sh[G3_LV + (g + rh * 8) * 68 + mc];
            float2 xv = *(const float2*)&X[((size_t)tc * BATCH + bi) * DIN + mc];
            float m0 = acc[rh*2] + bia.x, m1 = acc[rh*2 + 1] + bia.y;
            float d0 = xv.x - m0, d1 = xv.y - m1;
            local += mt * 0.5f * (LOG_2PI + lv.x + d0 * d0 * expf(-lv.x));
            local += mt * 0.5f * (LOG_2PI + lv.y + d1 * d1 * expf(-lv.y));
        }
    }
    float* red = sh + RED_OFF;
    red[tid] = local;
    __syncthreads();
    for (int s = 256; s > 0; s >>= 1) {
        if (tid < s) red[tid] += red[tid + s];
        __syncthreads();
    }
    if (tid == 0) g_reconpart[tc * 64 + bb2] = red[0];
    __syncthreads();
}

// ---- G2: Hpz = z@Wp1z / Hz = z@Wd1z (tf32 MMA, all 128 blocks) -------------
__device__ void g2_step(float* sh)
{
    const int tid = threadIdx.x;
    const int w = tid >> 5, lane = tid & 31, g = lane >> 2, tig = lane & 3;
    const int bid = blockIdx.x;
    const int mat = bid >> 6;
    const float* __restrict__ Wt = mat ? g_Wd1zt : g_Wp1zt;
    float* __restrict__ C = mat ? g_Hz : g_Hpz;
    const int idx = bid & 63;
    const int r0 = (idx >> 2) * 64;
    const int c0 = (idx & 3) * 128;
    const int mt_ = w & 3;
    const int n0 = (w >> 2) * 32;
    float acc[4][4] = {};

    const float* pA = sh + G2_A + (mt_ * 16 + g) * 36 + tig;
    const float* pB = sh + G2_B + tig * 136 + n0 + g;

    for (int k0 = 0; k0 < ZDIM; k0 += 32) {
        __syncthreads();
        {   // A staging: z 64x32
            int r  = tid >> 3;
            int c4 = (tid & 7) * 4;
            float4 z4 = ldcg4(&g_z[(size_t)(r0 + r) * ZDIM + k0 + c4]);
            uint4 u;
            u.x = f2tf(z4.x); u.y = f2tf(z4.y); u.z = f2tf(z4.z); u.w = f2tf(z4.w);
            *(uint4*)&sh[G2_A + r * 36 + c4] = u;
        }
        #pragma unroll
        for (int l = 0; l < 2; l++) {   // B staging: 32x128
            int v  = tid + l * 512;
            int r  = v >> 5;
            int c4 = (v & 31) * 4;
            *(uint4*)&sh[G2_B + r * 136 + c4] =
                *(const uint4*)&Wt[(size_t)(k0 + r) * HDIM + c0 + c4];
        }
        __syncthreads();
        #pragma unroll
        for (int kk = 0; kk < 4; kk++) {
            unsigned a[4] = { FU(pA[kk*8]), FU(pA[kk*8 + 288]),
                              FU(pA[kk*8 + 4]), FU(pA[kk*8 + 292]) };
            #pragma unroll
            for (int nt = 0; nt < 4; nt++) {
                unsigned b0 = FU(pB[kk*8*136 + nt*8]);
                unsigned b1 = FU(pB[(kk*8 + 4)*136 + nt*8]);
                mma8(acc[nt], a, b0, b1);
            }
        }
    }
    #pragma unroll
    for (int nt = 0; nt < 4; nt++) {
        int cc = c0 + n0 + nt * 8 + 2 * tig;
        int rr = r0 + mt_ * 16 + g;
        __stcg((float2*)&C[(size_t)rr * HDIM + cc], make_float2(acc[nt][0], acc[nt][1]));
        __stcg((float2*)&C[(size_t)(rr + 8) * HDIM + cc], make_float2(acc[nt][2], acc[nt][3]));
    }
}

__global__ void __launch_bounds__(NTHR, 1)
scan_tc(const float* __restrict__ bd2, const float* __restrict__ noise,
        const float* __restrict__ bp2, const float* __restrict__ X)
{
    __shared__ float sh[SH_TOTAL];
    const int tid = threadIdx.x;
    const int w = tid >> 5, lane = tid & 31, g = lane >> 2, tig = lane & 3;
    float zr[8];

    if (blockIdx.x < 64 && w < 8) {   // reg-resident z fragment
        int r0 = blockIdx.x * 16, n0 = (w & 7) * 16;
        #pragma unroll
        for (int nt = 0; nt < 2; nt++)
            #pragma unroll
            for (int rh = 0; rh < 2; rh++) {
                float2 z2 = ldcg2(&g_z[(size_t)(r0 + g + rh * 8) * ZDIM + n0 + nt * 8 + 2 * tig]);
                zr[nt * 4 + rh * 2] = z2.x;
                zr[nt * 4 + rh * 2 + 1] = z2.y;
            }
    }

    unsigned ls = 0;
    for (int t = 0; t < T_STEPS; t++) {
        if (blockIdx.x < 64) g1_step(t, bd2, noise, sh, zr);
        else if (t > 0)      g3_step(t - 1, bp2, X, sh);
        gridbar(ls);
        g2_step(sh);
        gridbar(ls);
    }
    if (blockIdx.x >= 64) g3_step(T_STEPS - 1, bp2, X, sh);
}

// ---------------- outputs ---------------------------------------------------
__global__ void copy_z(float* __restrict__ out)
{
    int i = blockIdx.x * blockDim.x + threadIdx.x;
    out[i] = g_z[i];
}

__global__ void finalize(float* __restrict__ out, int out_size)
{
    int tid = threadIdx.x;   // 256
    float k = 0.f, r = 0.f;
    for (int i = tid; i < T_STEPS * 64; i += 256) k += g_kldpart[i];
    for (int i = tid; i < T_STEPS * 64; i += 256) r += g_reconpart[i];
    __shared__ float rk[256], rr[256];
    rk[tid] = k; rr[tid] = r;
    __syncthreads();
    for (int s = 128; s > 0; s >>= 1) {
        if (tid < s) { rk[tid] += rk[tid + s]; rr[tid] += rr[tid + s]; }
        __syncthreads();
    }
    if (tid == 0) {
        float kld   = rk[0] * (0.5f * DT / (float)BS);
        float recon = rr[0] * (1.f / (float)BS);
        out[out_size - 3] = recon + kld;
        out[out_size - 2] = recon;
        out[out_size - 1] = kld;
    }
}

// ---------------- launch ----------------------------------------------------
extern "C" void kernel_launch(void* const* d_in, const int* in_sizes, int n_in,
                              void* d_out, int out_size)
{
    const float* X     = (const float*)d_in[0];
    const float* M     = (const float*)d_in[1];
    const float* cov   = (const float*)d_in[2];
    const float* ph    = (const float*)d_in[3];
    const float* phpos = (const float*)d_in[4];
    const float* noise = (const float*)d_in[5];
    const float* Wc1 = (const float*)d_in[6],  *bc1 = (const float*)d_in[7];
    const float* Wc2 = (const float*)d_in[8],  *bc2 = (const float*)d_in[9];
    const float* Wd1 = (const float*)d_in[10], *bd1 = (const float*)d_in[11];
    const float* Wd2 = (const float*)d_in[12], *bd2 = (const float*)d_in[13];
    const float* Wf1 = (const float*)d_in[14], *bf1 = (const float*)d_in[15];
    const float* Wf2 = (const float*)d_in[16], *bf2 = (const float*)d_in[17];
    const float* Wp1 = (const float*)d_in[18], *bp1 = (const float*)d_in[19];
    const float* Wp2 = (const float*)d_in[20], *bp2 = (const float*)d_in[21];
    float* out = (float*)d_out;

    float *pHh, *pHhpos, *pHph, *pHf, *pdiff, *pz, *pHz;
    cudaGetSymbolAddress((void**)&pHh,    g_Hh);
    cudaGetSymbolAddress((void**)&pHhpos, g_Hhpos);
    cudaGetSymbolAddress((void**)&pHph,   g_Hph);
    cudaGetSymbolAddress((void**)&pHf,    g_Hf);
    cudaGetSymbolAddress((void**)&pdiff,  g_diff);
    cudaGetSymbolAddress((void**)&pz,     g_z);
    cudaGetSymbolAddress((void**)&pHz,    g_Hz);

    // ---- precompute (parallel over all T) ----
    z0_kernel<<<BATCH, 128>>>(cov, Wc1, bc1, Wc2, bc2);
    mt_kernel<<<64, 256>>>(M);
    cvt_weights<<<256, 256>>>(Wd2, Wp1, Wd1, Wp2);
    gemm_f32<0, false><<<dim3(HDIM/64, TB/64), 256>>>(ph,  nullptr, Wd1, bd1, pHh,    TB, HDIM, RDIM);
    gemm_f32<0, true ><<<dim3(HDIM/64, TB/64), 256>>>(ph,  phpos,   Wd1, bd1, pHhpos, TB, HDIM, RDIM);
    gemm_f32<0, false><<<dim3(HDIM/64, TB/64), 256>>>(ph,  nullptr, Wp1, bp1, pHph,   TB, HDIM, RDIM);
    gemm_f32<1, false><<<dim3(HDIM/64, TB/64), 256>>>(ph,  nullptr, Wf1, bf1, pHf,    TB, HDIM, RDIM);
    gemm_f32<2, false><<<dim3(ZDIM/64, TB/64), 256>>>(pHf, nullptr, Wf2, bf2, pdiff,  TB, ZDIM, HDIM);

    // initial Hz = z0 @ Wd1[R:,:]  (fp32)
    gemm_f32<0, false><<<dim3(HDIM/64, BS/64), 256>>>(pz, nullptr, Wd1 + RDIM * HDIM,
                                                      nullptr, pHz, BS, HDIM, ZDIM);

    // ---- persistent tf32 scan ----
    scan_tc<<<NBLK, NTHR>>>(bd2, noise, bp2, X);

    // ---- outputs ----
    copy_z<<<(BS * ZDIM) / 256, 256>>>(out);
    finalize<<<1, 256>>>(out, out_size);
}